// round 1
// baseline (speedup 1.0000x reference)
#include <cuda_runtime.h>

// CurrentFactorCell: out_re = s0*(zr*gr - zi*gi) + m0*(zr*gr + zi*gi) + b0
//                    out_im = s1*(zr*gi + zi*gr) + m1*(zi*gr - zr*gi) + b1
// Simplified with per-launch-constant scalars:
//   out_re = cRR*zr*gr + cII*zi*gi + b0,  cRR = s0+m0, cII = m0-s0
//   out_im = cRI*zr*gi + cIR*zi*gr + b1,  cRI = s1-m1, cIR = s1+m1
//
// Pure HBM-bound elementwise op. float4 everywhere, 4 elems/thread.

__global__ void __launch_bounds__(256)
cfc_kernel(const float4* __restrict__ zr4,
           const float4* __restrict__ zi4,
           const float4* __restrict__ g4,     // interleaved (re,im) pairs
           const float*  __restrict__ scale,
           const float*  __restrict__ mix,
           const float*  __restrict__ bias,
           float* __restrict__ out_re,
           float* __restrict__ out_im,
           int n4)
{
    int i = blockIdx.x * blockDim.x + threadIdx.x;
    if (i >= n4) return;

    // 6 scalars: broadcast loads, L1/L2 resident after first warp.
    float s0 = __ldg(&scale[0]), s1 = __ldg(&scale[1]);
    float m0 = __ldg(&mix[0]),   m1 = __ldg(&mix[1]);
    float b0 = __ldg(&bias[0]),  b1 = __ldg(&bias[1]);
    float cRR = s0 + m0;   // coeff for zr*gr in out_re
    float cII = m0 - s0;   // coeff for zi*gi in out_re
    float cRI = s1 - m1;   // coeff for zr*gi in out_im
    float cIR = s1 + m1;   // coeff for zi*gr in out_im

    float4 zr = zr4[i];
    float4 zi = zi4[i];
    // gate is (N,2) interleaved: 2 float4 cover 4 elements
    float4 ga = g4[2 * i + 0];   // (gr0, gi0, gr1, gi1)
    float4 gb = g4[2 * i + 1];   // (gr2, gi2, gr3, gi3)

    float4 ore, oim;
    ore.x = fmaf(cRR, zr.x * ga.x, fmaf(cII, zi.x * ga.y, b0));
    oim.x = fmaf(cRI, zr.x * ga.y, fmaf(cIR, zi.x * ga.x, b1));
    ore.y = fmaf(cRR, zr.y * ga.z, fmaf(cII, zi.y * ga.w, b0));
    oim.y = fmaf(cRI, zr.y * ga.w, fmaf(cIR, zi.y * ga.z, b1));
    ore.z = fmaf(cRR, zr.z * gb.x, fmaf(cII, zi.z * gb.y, b0));
    oim.z = fmaf(cRI, zr.z * gb.y, fmaf(cIR, zi.z * gb.x, b1));
    ore.w = fmaf(cRR, zr.w * gb.z, fmaf(cII, zi.w * gb.w, b0));
    oim.w = fmaf(cRI, zr.w * gb.w, fmaf(cIR, zi.w * gb.z, b1));

    reinterpret_cast<float4*>(out_re)[i] = ore;
    reinterpret_cast<float4*>(out_im)[i] = oim;
}

extern "C" void kernel_launch(void* const* d_in, const int* in_sizes, int n_in,
                              void* d_out, int out_size)
{
    const float* z_re  = (const float*)d_in[0];
    const float* z_im  = (const float*)d_in[1];
    const float* gate  = (const float*)d_in[2];
    const float* scale = (const float*)d_in[3];
    const float* mix   = (const float*)d_in[4];
    const float* bias  = (const float*)d_in[5];

    int n = in_sizes[0];            // 8388608
    int n4 = n / 4;                 // divisible by 4

    float* out_re = (float*)d_out;
    float* out_im = (float*)d_out + n;

    int threads = 256;
    int blocks = (n4 + threads - 1) / threads;
    cfc_kernel<<<blocks, threads>>>(
        (const float4*)z_re, (const float4*)z_im, (const float4*)gate,
        scale, mix, bias, out_re, out_im, n4);
}